// round 17
// baseline (speedup 1.0000x reference)
#include <cuda_runtime.h>
#include <cuda_bf16.h>
#include <cstdint>
#include <math.h>

// ---------------- problem constants ----------------
#define BB 4
#define CC 21
#define HWP 16384      // 128*128
#define DD 256
#define AA 84          // B*C anchor rows
#define VV 100         // views per anchor
#define NROW 8400      // A*V
#define NPAD 8448      // padded to 66*128
#define POS 400        // positives per row (incl. self)
#define NCB 66         // column blocks of 128
#define NSW (NCB*4)    // neg-sum partial slots per row
#define NTRI 2211      // 66*67/2 upper-triangle blocks
#define NPADCOL 48.0f  // pad columns contribute exp(0)=1 each to every row sum
#define GEMM_GRID 304  // 2 CTAs per SM x 152 SMs (GB300)

// ---------------- device scratch (static, no allocs) ----------------
__device__ int   g_pred[BB*HWP];
__device__ int   g_idx[AA*VV];
__device__ __align__(16) __nv_bfloat16 g_cfb[(size_t)NPAD*DD];  // class-major normalized bf16 features
__device__ __align__(16) float g_P[(size_t)NROW*POS];        // positive logits (row-class band)
__device__ __align__(16) float g_NSpart[(size_t)NROW*NSW];   // per (row, block-group, sub) exp-sum partials
__device__ float g_rowval[NROW];
__device__ int   g_cnt;                        // last-block counter (reset by last block)

// ---------------- helpers ----------------
__device__ __forceinline__ uint32_t smem_u32(const void* p){
    uint32_t a;
    asm("{ .reg .u64 t; cvta.to.shared.u64 t, %1; cvt.u32.u64 %0, t; }" : "=r"(a) : "l"(p));
    return a;
}
__device__ __forceinline__ void ldsm4(uint32_t* r, uint32_t addr){
    asm volatile("ldmatrix.sync.aligned.m8n8.x4.shared.b16 {%0,%1,%2,%3}, [%4];"
        : "=r"(r[0]), "=r"(r[1]), "=r"(r[2]), "=r"(r[3]) : "r"(addr));
}
__device__ __forceinline__ void mma16816(float* d, const uint32_t* a, uint32_t b0, uint32_t b1){
    asm volatile("mma.sync.aligned.m16n8k16.row.col.f32.bf16.bf16.f32 "
        "{%0,%1,%2,%3}, {%4,%5,%6,%7}, {%8,%9}, {%0,%1,%2,%3};"
        : "+f"(d[0]), "+f"(d[1]), "+f"(d[2]), "+f"(d[3])
        : "r"(a[0]), "r"(a[1]), "r"(a[2]), "r"(a[3]), "r"(b0), "r"(b1));
}
__device__ __forceinline__ void cpasync16(uint32_t saddr, const void* gaddr){
    asm volatile("cp.async.cg.shared.global [%0], [%1], 16;" :: "r"(saddr), "l"(gaddr));
}
__device__ __forceinline__ float fex2(float x){
    float r;
    asm("ex2.approx.f32 %0, %1;" : "=f"(r) : "f"(x));
    return r;
}
// decode upper-triangle block index -> (bi, bj), bi <= bj
__device__ __forceinline__ void tri_decode(int m, int& bi, int& bj){
    int lo = (int)((133.0 - sqrt(17689.0 - 8.0*(double)m)) * 0.5);
    while ((lo+1)*(133-(lo+1))/2 <= m) lo++;
    while (lo*(133-lo)/2 > m) lo--;
    bi = lo; bj = lo + (m - lo*(133-lo)/2);
}

// ---------------- kernel 1: bilinear upsample (64->128) + argmax, 2x2 quad/thread ----------------
// Bit-exact same expression tree as per-pixel reference path (col-interp then row-interp).
__global__ void k_pred(const float* __restrict__ predict){
    int tid = blockIdx.x*blockDim.x + threadIdx.x;
    if (tid >= BB*4096) return;
    int b = tid >> 12;
    int q = tid & 4095;
    int v = q >> 6, u = q & 63;
    const float* pb = predict + (size_t)b*CC*4096;
    int rm = max(v-1,0), r0 = v, rp = min(v+1,63);
    int cm = max(u-1,0), c0 = u, cp = min(u+1,63);
    float best0=-3.4e38f, best1=-3.4e38f, best2=-3.4e38f, best3=-3.4e38f;
    int bc0=0, bc1=0, bc2=0, bc3=0;
    #pragma unroll
    for (int c = 0; c < CC; c++){
        const float* pc = pb + c*4096;
        float a00=pc[rm*64+cm], a01=pc[rm*64+c0], a02=pc[rm*64+cp];
        float a10=pc[r0*64+cm], a11=pc[r0*64+c0], a12=pc[r0*64+cp];
        float a20=pc[rp*64+cm], a21=pc[rp*64+c0], a22=pc[rp*64+cp];
        // horizontal interp per row: left uses cols (cm,c0) w=0.75; right uses (c0,cp) w=0.25
        float hl0 = a00 + 0.75f*(a01-a00), hr0 = a01 + 0.25f*(a02-a01);
        float hl1 = a10 + 0.75f*(a11-a10), hr1 = a11 + 0.25f*(a12-a11);
        float hl2 = a20 + 0.75f*(a21-a20), hr2 = a21 + 0.25f*(a22-a21);
        // vertical: top pixels rows (rm,r0) w=0.75; bottom rows (r0,rp) w=0.25
        float p0 = hl0 + 0.75f*(hl1-hl0);   // (2v,   2u)
        float p1 = hr0 + 0.75f*(hr1-hr0);   // (2v,   2u+1)
        float p2 = hl1 + 0.25f*(hl2-hl1);   // (2v+1, 2u)
        float p3 = hr1 + 0.25f*(hr2-hr1);   // (2v+1, 2u+1)
        if (p0 > best0){ best0 = p0; bc0 = c; }
        if (p1 > best1){ best1 = p1; bc1 = c; }
        if (p2 > best2){ best2 = p2; bc2 = c; }
        if (p3 > best3){ best3 = p3; bc3 = c; }
    }
    int base = b*HWP + (2*v)*128 + 2*u;
    g_pred[base]       = bc0;
    g_pred[base+1]     = bc1;
    g_pred[base+128]   = bc2;
    g_pred[base+129]   = bc3;
}

// ---------------- kernel 2: per-(b,c) hard/easy selection (deterministic rank-based) ----------------
__global__ void k_select(const int* __restrict__ labels){
    __shared__ int sh_h[256], sh_e[256], sh_ph[256], sh_pe[256];
    __shared__ int s_hk, s_ek, s_S;
    int row = blockIdx.x;
    int b = row / CC, c = row % CC;
    int t = threadIdx.x;
    unsigned long long hbits = 0ull, ebits = 0ull;
    int base = b*HWP + t*64;
    for (int q = 0; q < 64; q++){
        int pr = g_pred[base+q];
        int lb = labels[base+q];
        if (pr == c){ if (lb == c) ebits |= (1ull<<q); else hbits |= (1ull<<q); }
    }
    sh_h[t] = __popcll(hbits); sh_e[t] = __popcll(ebits);
    __syncthreads();
    if (t == 0){
        int rh = 0, re = 0;
        for (int u = 0; u < 256; u++){ sh_ph[u]=rh; sh_pe[u]=re; rh+=sh_h[u]; re+=sh_e[u]; }
        int nh = rh, ne = re;
        int hk;
        if (nh >= 50 && ne >= 50) hk = 50;
        else if (nh >= 50)        hk = 100 - ne;
        else                      hk = nh;
        int ek = 100 - hk;
        s_hk = hk; s_ek = ek;
        s_S = min(nh, hk) + min(ne, ek);
    }
    __syncthreads();
    int hb = sh_ph[t], eb = sh_pe[t];
    int hk = s_hk, ek = s_ek, S = s_S;
    for (int q = 0; q < 64; q++){
        int p = t*64 + q;
        int slot;
        if ((hbits>>q)&1ull){
            if (hb < hk) slot = hb + min(eb, ek);
            else         slot = S + (p - min(hb,hk) - min(eb,ek));
            hb++;
        } else if ((ebits>>q)&1ull){
            if (eb < ek) slot = min(hb, hk) + eb;
            else         slot = S + (p - min(hb,hk) - min(eb,ek));
            eb++;
        } else {
            slot = S + (p - min(hb,hk) - min(eb,ek));
        }
        if (slot < VV) g_idx[row*VV + slot] = p;
    }
}

// ---------------- kernel 3: gather + L2-normalize -> bf16, CLASS-MAJOR rows ----------------
// row n = c*400 + b*100 + v  (all 400 same-class rows contiguous)
__global__ void k_gather(const float* __restrict__ feats){
    int gw   = (blockIdx.x*blockDim.x + threadIdx.x) >> 5;
    int lane = threadIdx.x & 31;
    if (gw >= NPAD) return;
    if (gw >= NROW){   // zero the pad rows every call (deterministic)
        #pragma unroll
        for (int q = 0; q < 8; q++) g_cfb[(size_t)gw*DD + lane + 32*q] = __float2bfloat16(0.0f);
        return;
    }
    int a = gw / VV, v = gw % VV;
    int b = a / CC, c = a % CC;
    int p = g_idx[gw];
    const float* fb = feats + (size_t)b*DD*HWP + p;
    float vals[8]; float ss = 0.f;
    #pragma unroll
    for (int q = 0; q < 8; q++){
        vals[q] = fb[(size_t)(lane + 32*q)*HWP];
        ss += vals[q]*vals[q];
    }
    #pragma unroll
    for (int m = 16; m > 0; m >>= 1) ss += __shfl_xor_sync(0xffffffffu, ss, m);
    float sc = 1.0f / fmaxf(sqrtf(ss), 1e-12f);
    int n = c*400 + b*100 + v;
    #pragma unroll
    for (int q = 0; q < 8; q++) g_cfb[(size_t)n*DD + lane + 32*q] = __float2bfloat16(vals[q]*sc);
}

// ---------------- kernel 4: PERSISTENT symmetric HMMA Gram, cross-tile cp.async ring ----------------
#define SMEM_GEMM (3*32768)
#define STG 32768       // stage stride
#define BOFF 16384      // B tile offset within stage

__global__ __launch_bounds__(256, 2) void k_gemm(){
    extern __shared__ char sm[];
    int t = threadIdx.x;
    int lane = t & 31, wid = t >> 5;
    uint32_t sbase = smem_u32(sm);
    const char* base = (const char*)g_cfb;
    const int G = gridDim.x;

    int wm = wid & 3, wn = wid >> 2;
    int ra = wm*32 + (lane & 7) + ((lane >> 3) & 1) * 8;
    int ca = lane >> 4;
    int rb = wn*64 + (lane & 7) + (lane >> 4) * 8;
    int cb = (lane >> 3) & 1;

    // loader: 128 rows x 64 bf16 chunk of both tiles into stage st
    auto prefetch = [&](uint32_t aoff, uint32_t boff, int kc, int st){
        uint32_t sb = sbase + st*STG;
        uint32_t koff = (uint32_t)kc*128;
        #pragma unroll
        for (int u = 0; u < 4; u++){
            int idx = t + u*256;
            int r = idx >> 3, c = idx & 7;
            uint32_t so = (uint32_t)(r*128 + ((c ^ r) & 7)*16);
            uint32_t go = (uint32_t)r*512 + koff + (uint32_t)c*16;
            cpasync16(sb + so,         base + aoff + go);
            cpasync16(sb + BOFF + so,  base + boff + go);
        }
        asm volatile("cp.async.commit_group;" ::: "memory");
    };

    // ---- prefetch state (leads consume by 2 chunks) ----
    int p_tile = blockIdx.x;
    int pbi, pbj; tri_decode(p_tile, pbi, pbj);
    uint32_t p_aoff = (uint32_t)pbi*65536u, p_boff = (uint32_t)pbj*65536u;
    int p_kc = 0, p_st = 0;
    prefetch(p_aoff, p_boff, 0, 0);
    prefetch(p_aoff, p_boff, 1, 1);
    p_kc = 2; p_st = 2;
    int c_st = 0;   // consume stage

    for (int tile = blockIdx.x; tile < NTRI; tile += G){
        int bi, bj; tri_decode(tile, bi, bj);
        int i0 = bi*128, j0 = bj*128;
        bool offdiag = (bi != bj);
        bool last_tile = (tile + G >= NTRI);

        int ca0 = i0/400, ca1 = (i0+127)/400;
        bool has_pos = ((j0 < ca0*400+400) && (j0+128 > ca0*400)) ||
                       ((j0 < ca1*400+400) && (j0+128 > ca1*400));

        float acc[2][8][4];
        #pragma unroll
        for (int mi = 0; mi < 2; mi++)
            #pragma unroll
            for (int nj = 0; nj < 8; nj++)
                #pragma unroll
                for (int q = 0; q < 4; q++) acc[mi][nj][q] = 0.f;

        #pragma unroll
        for (int kc = 0; kc < 4; kc++){
            if (last_tile && kc == 3) asm volatile("cp.async.wait_group 0;" ::: "memory");
            else                      asm volatile("cp.async.wait_group 1;" ::: "memory");
            __syncthreads();
            // prefetch 2-ahead chunk (may belong to the next tile)
            if (p_kc < 4){
                prefetch(p_aoff, p_boff, p_kc, p_st);
                p_st = (p_st == 2) ? 0 : p_st + 1;
                p_kc++;
                if (p_kc == 4){
                    p_tile += G;
                    if (p_tile < NTRI){
                        tri_decode(p_tile, pbi, pbj);
                        p_aoff = (uint32_t)pbi*65536u;
                        p_boff = (uint32_t)pbj*65536u;
                        p_kc = 0;
                    }
                }
            }
            uint32_t sb = sbase + c_st*STG;
            c_st = (c_st == 2) ? 0 : c_st + 1;
            #pragma unroll
            for (int ks = 0; ks < 4; ks++){
                int c0 = ks*2;
                uint32_t a[2][4];
                #pragma unroll
                for (int mi = 0; mi < 2; mi++){
                    int r = ra + mi*16;
                    int c = c0 + ca;
                    uint32_t addr = sb + (uint32_t)(r*128 + (((c ^ r) & 7))*16);
                    ldsm4(a[mi], addr);
                }
                #pragma unroll
                for (int nb = 0; nb < 4; nb++){
                    int r = rb + nb*16;
                    int c = c0 + cb;
                    uint32_t addr = sb + BOFF + (uint32_t)(r*128 + (((c ^ r) & 7))*16);
                    uint32_t b[4];
                    ldsm4(b, addr);
                    mma16816(acc[0][2*nb],   a[0], b[0], b[1]);
                    mma16816(acc[0][2*nb+1], a[0], b[2], b[3]);
                    mma16816(acc[1][2*nb],   a[1], b[0], b[1]);
                    mma16816(acc[1][2*nb+1], a[1], b[2], b[3]);
                }
            }
        }

        // ---- epilogue (overlaps the already-inflight next-tile prefetches) ----
        const float EC = 14.42695040888963f;   // 10 * log2(e)
        int r00 = i0 + wm*32 + (lane >> 2);
        int irow[2][2]; int ilo[2][2]; bool iok[2][2];
        #pragma unroll
        for (int mi = 0; mi < 2; mi++)
            #pragma unroll
            for (int h = 0; h < 2; h++){
                irow[mi][h] = r00 + mi*16 + h*8;
                iok[mi][h]  = irow[mi][h] < NROW;
                ilo[mi][h]  = (irow[mi][h] / 400) * 400;
            }
        float rs[2][2] = {{0.f,0.f},{0.f,0.f}};
        float rsc[16];
        #pragma unroll
        for (int q = 0; q < 16; q++) rsc[q] = 0.f;

        int jc_base = j0 + wn*64 + (lane & 3)*2;

        if (!has_pos){
            #pragma unroll
            for (int nj = 0; nj < 8; nj++){
                #pragma unroll
                for (int mi = 0; mi < 2; mi++){
                    #pragma unroll
                    for (int h = 0; h < 2; h++){
                        float e0 = fex2(acc[mi][nj][h*2+0] * EC);
                        float e1 = fex2(acc[mi][nj][h*2+1] * EC);
                        rs[mi][h] += e0 + e1;
                        rsc[nj*2+0] += e0;
                        rsc[nj*2+1] += e1;
                    }
                }
            }
        } else {
            #pragma unroll
            for (int nj = 0; nj < 8; nj++){
                int jc = jc_base + nj*8;
                #pragma unroll
                for (int mi = 0; mi < 2; mi++){
                    #pragma unroll
                    for (int h = 0; h < 2; h++){
                        int i  = irow[mi][h];
                        int lo = ilo[mi][h];
                        #pragma unroll
                        for (int p = 0; p < 2; p++){
                            float a = acc[mi][nj][h*2+p];
                            int j = jc + p;
                            if ((unsigned)(j - lo) < 400u){
                                if (iok[mi][h]){
                                    float l = a * 10.0f;
                                    g_P[(size_t)i*POS + (j - lo)] = l;
                                    if (offdiag) g_P[(size_t)j*POS + (i - lo)] = l;
                                }
                            } else {
                                float e = fex2(a * EC);
                                rs[mi][h] += e;
                                rsc[nj*2+p] += e;
                            }
                        }
                    }
                }
            }
        }

        #pragma unroll
        for (int ms = 1; ms <= 2; ms <<= 1)
            #pragma unroll
            for (int mi = 0; mi < 2; mi++)
                #pragma unroll
                for (int h = 0; h < 2; h++)
                    rs[mi][h] += __shfl_xor_sync(0xffffffffu, rs[mi][h], ms);
        if ((lane & 3) == 0){
            #pragma unroll
            for (int mi = 0; mi < 2; mi++)
                #pragma unroll
                for (int h = 0; h < 2; h++)
                    if (iok[mi][h]){
                        g_NSpart[(size_t)irow[mi][h]*NSW + bj*4 + wn]     = rs[mi][h];
                        g_NSpart[(size_t)irow[mi][h]*NSW + bj*4 + 2 + wn] = 0.f;
                    }
        }

        if (offdiag){
            #pragma unroll
            for (int ms = 4; ms <= 16; ms <<= 1)
                #pragma unroll
                for (int q = 0; q < 16; q++)
                    rsc[q] += __shfl_xor_sync(0xffffffffu, rsc[q], ms);
            if ((lane >> 2) == 0){
                #pragma unroll
                for (int nj = 0; nj < 8; nj++){
                    #pragma unroll
                    for (int p = 0; p < 2; p++){
                        int j = jc_base + nj*8 + p;
                        if (j < NROW) g_NSpart[(size_t)j*NSW + bi*4 + wm] = rsc[nj*2+p];
                    }
                }
            }
        }
    }
}

// ---------------- kernel 5: per-row finalize + fused deterministic final reduction ----------------
__global__ void k_finalize(float* __restrict__ out){
    __shared__ float sh[256];
    __shared__ int s_last;
    int gw   = (blockIdx.x*blockDim.x + threadIdx.x) >> 5;
    int lane = threadIdx.x & 31;

    float ns = 0.f;
    const float4* np = (const float4*)&g_NSpart[(size_t)gw*NSW];
    for (int j4 = lane; j4 < NSW/4; j4 += 32){
        float4 v = np[j4];
        ns += (v.x + v.y) + (v.z + v.w);
    }
    #pragma unroll
    for (int m = 16; m > 0; m >>= 1) ns += __shfl_xor_sync(0xffffffffu, ns, m);
    ns -= NPADCOL;
    int kself = gw - (gw/400)*400;
    float acc = 0.f;
    const float4* pp = (const float4*)&g_P[(size_t)gw*POS];
    for (int k4 = lane; k4 < POS/4; k4 += 32){
        float4 v = pp[k4];
        float l[4] = {v.x, v.y, v.z, v.w};
        #pragma unroll
        for (int e = 0; e < 4; e++){
            int k = k4*4 + e;
            if (k == kself) continue;
            acc += l[e] - __logf(__expf(l[e]) + ns);
        }
    }
    #pragma unroll
    for (int m = 16; m > 0; m >>= 1) acc += __shfl_xor_sync(0xffffffffu, acc, m);
    if (lane == 0) g_rowval[gw] = acc / 399.0f;

    __threadfence();
    __syncthreads();
    if (threadIdx.x == 0) s_last = (atomicAdd(&g_cnt, 1) == (int)gridDim.x - 1);
    __syncthreads();
    if (s_last){
        __threadfence();
        int t = threadIdx.x;
        float s = 0.f;
        for (int i = t; i < NROW; i += 256) s += g_rowval[i];
        sh[t] = s; __syncthreads();
        for (int mm = 128; mm > 0; mm >>= 1){
            if (t < mm) sh[t] += sh[t+mm];
            __syncthreads();
        }
        if (t == 0){ out[0] = -(sh[0] / (float)NROW); g_cnt = 0; }
    }
}

// ---------------- launch ----------------
extern "C" void kernel_launch(void* const* d_in, const int* in_sizes, int n_in,
                              void* d_out, int out_size){
    const float* feats   = nullptr;
    const float* predict = nullptr;
    const int*   labels  = nullptr;
    for (int i = 0; i < n_in; i++){
        if      (in_sizes[i] == BB*DD*HWP)   feats   = (const float*)d_in[i];
        else if (in_sizes[i] == BB*CC*4096)  predict = (const float*)d_in[i];
        else if (in_sizes[i] == BB*HWP)      labels  = (const int*)d_in[i];
    }
    cudaFuncSetAttribute(k_gemm, cudaFuncAttributeMaxDynamicSharedMemorySize, SMEM_GEMM);
    k_pred<<<(BB*4096+255)/256, 256>>>(predict);
    k_select<<<AA, 256>>>(labels);
    k_gather<<<NPAD/8, 256>>>(feats);
    k_gemm<<<GEMM_GRID, 256, SMEM_GEMM>>>();
    k_finalize<<<NROW/8, 256>>>((float*)d_out);
}